// round 11
// baseline (speedup 1.0000x reference)
#include <cuda_runtime.h>

#define NTHR   256
#define CPB    1024LL          // float4 per block chunk = 16 KB
#define NPART  16384           // blocks for 8192^2 (n4 / CPB)

// Scratch (no allocations). g_count wraps each run -> graph-replay safe.
__device__ double       g_partials[NPART];
__device__ float        g_total;
__device__ unsigned int g_count;

// ---------------------------------------------------------------------------
// Kernel 1: one-shot block reduction. Block b reduces the (nblk-1-b)-th chunk
// (descending addresses -> the lowest ~L2-capacity of x is the freshest
// residue for the ascending add kernel). Last-arriving block folds all
// partials and computes the closed-form scalar.
// ---------------------------------------------------------------------------
__global__ void __launch_bounds__(NTHR) reduce_kernel(const float4* __restrict__ x4,
                                                      long long n4)
{
    const long long nblk = n4 / CPB;                       // == gridDim.x
    const long long c    = nblk - 1 - (long long)blockIdx.x;   // descending map
    const float4* base   = x4 + c * CPB + threadIdx.x;

    float4 v0 = base[0];
    float4 v1 = base[256];
    float4 v2 = base[512];
    float4 v3 = base[768];

    float s0 = (v0.x + v0.y) + (v0.z + v0.w);
    float s1 = (v1.x + v1.y) + (v1.z + v1.w);
    float s2 = (v2.x + v2.y) + (v2.z + v2.w);
    float s3 = (v3.x + v3.y) + (v3.z + v3.w);

    double acc = ((double)s0 + (double)s1) + ((double)s2 + (double)s3);

    __shared__ double sdata[NTHR];
    sdata[threadIdx.x] = acc;
    __syncthreads();
    for (int s = NTHR/2; s > 0; s >>= 1) {
        if (threadIdx.x < s) sdata[threadIdx.x] += sdata[threadIdx.x + s];
        __syncthreads();
    }

    __shared__ bool s_isLast;
    if (threadIdx.x == 0) {
        g_partials[blockIdx.x] = sdata[0];
        __threadfence();
        unsigned v = atomicInc(&g_count, gridDim.x - 1);   // wraps -> replay-safe
        s_isLast = (v == gridDim.x - 1);
    }
    __syncthreads();

    if (s_isLast) {
        // Fold 16384 partials: 64 per thread, fixed order -> deterministic.
        double facc = 0.0;
        const long long np = nblk;
        for (long long k = threadIdx.x; k < np; k += NTHR) facc += g_partials[k];
        sdata[threadIdx.x] = facc;
        __syncthreads();
        for (int s = NTHR/2; s > 0; s >>= 1) {
            if (threadIdx.x < s) sdata[threadIdx.x] += sdata[threadIdx.x + s];
            __syncthreads();
        }
        if (threadIdx.x == 0) {
            float  sf = (float)sdata[0];        // mimic jnp.sum's fp32 result
            double nn = trunc((double)sf);
            double tt = (nn > 1.0) ? nn * (nn - 1.0) * 0.5 : 0.0;
            g_total = (float)tt;
        }
    }
}

// ---------------------------------------------------------------------------
// Kernel 2: one-shot add, block b takes chunk b ASCENDING: the first waves
// re-read the low-address lines the reduce left in L2. __ldcs reads don't
// pollute; __stcs writes don't evict the residue.
// ---------------------------------------------------------------------------
__global__ void __launch_bounds__(NTHR) add_kernel(const float4* __restrict__ x4,
                                                   float4* __restrict__ out4)
{
    const long long c  = (long long)blockIdx.x;            // ascending map
    const float4* src  = x4   + c * CPB + threadIdx.x;
    float4*       dst  = out4 + c * CPB + threadIdx.x;

    const float t = g_total;                               // L2-broadcast scalar

    float4 v0 = __ldcs(src);
    float4 v1 = __ldcs(src + 256);
    float4 v2 = __ldcs(src + 512);
    float4 v3 = __ldcs(src + 768);

    v0.x += t; v0.y += t; v0.z += t; v0.w += t;
    v1.x += t; v1.y += t; v1.z += t; v1.w += t;
    v2.x += t; v2.y += t; v2.z += t; v2.w += t;
    v3.x += t; v3.y += t; v3.z += t; v3.w += t;

    __stcs(dst,       v0);
    __stcs(dst + 256, v1);
    __stcs(dst + 512, v2);
    __stcs(dst + 768, v3);
}

extern "C" void kernel_launch(void* const* d_in, const int* in_sizes, int n_in,
                              void* d_out, int out_size)
{
    const float4* x4   = (const float4*)d_in[0];
    float4*       out4 = (float4*)d_out;
    long long n  = (long long)in_sizes[0];   // 8192*8192 = 67,108,864
    long long n4 = n >> 2;                   // 16,777,216; n4 % CPB == 0
    unsigned nblk = (unsigned)(n4 / CPB);    // 16384

    reduce_kernel<<<nblk, NTHR>>>(x4, n4);
    add_kernel<<<nblk, NTHR>>>(x4, out4);
}

// round 12
// speedup vs baseline: 1.5152x; 1.5152x over previous
#include <cuda_runtime.h>

#define NBLK 296               // 148 SMs x 2 resident CTAs (best measured config)
#define NTHR 512
#define CHUNK 2048LL           // float4 per chunk = 32 KB
#define CHUNK_BYTES 32768

// Scratch (no allocations). State overwritten each run, wraps (g_count), or is
// monotonic with entry-captured baseline (g_epoch) -> graph-replay safe.
__device__ double                g_partials[NBLK];
__device__ float                 g_total;
__device__ unsigned int          g_count;
__device__ volatile unsigned int g_epoch;

__device__ __forceinline__ unsigned smem_u32(const void* p) {
    unsigned a;
    asm("{ .reg .u64 t; cvta.to.shared.u64 t, %1; cvt.u32.u64 %0, t; }"
        : "=r"(a) : "l"(p));
    return a;
}

__global__ void __launch_bounds__(NTHR, 2) fused_kernel(const float4* __restrict__ x4,
                                                        float4* __restrict__ out4,
                                                        long long n4)
{
    extern __shared__ float4 sbuf[];               // 2 x CHUNK float4 = 64 KB

    const long long nch     = n4 / CHUNK;          // 8192 for 8192^2
    const long long n4_main = nch * CHUNK;
    const long long tid     = (long long)blockIdx.x * blockDim.x + threadIdx.x;
    const long long gstride = (long long)gridDim.x * blockDim.x;

    const unsigned epoch0 = g_epoch;   // capture before any arrival can fire

    // -------- Phase 1: reduction, chunks walked DESCENDING (unchanged) ------
    float s0=0.f, s1=0.f, s2=0.f, s3=0.f;

    for (long long c = nch - 1 - blockIdx.x; c >= 0; c -= NBLK) {
        const float4* base = x4 + c * CHUNK + threadIdx.x;
        float4 v0 = base[0];
        float4 v1 = base[512];
        float4 v2 = base[1024];
        float4 v3 = base[1536];
        s0 += (v0.x + v0.y) + (v0.z + v0.w);
        s1 += (v1.x + v1.y) + (v1.z + v1.w);
        s2 += (v2.x + v2.y) + (v2.z + v2.w);
        s3 += (v3.x + v3.y) + (v3.z + v3.w);
    }
    for (long long i = n4_main + tid; i < n4; i += gstride) {   // tail (empty here)
        float4 v = x4[i];
        s0 += (v.x + v.y) + (v.z + v.w);
    }

    double acc = ((double)s0 + (double)s1) + ((double)s2 + (double)s3);

    __shared__ double sdata[NTHR];
    sdata[threadIdx.x] = acc;
    __syncthreads();
    for (int s = NTHR/2; s > 0; s >>= 1) {
        if (threadIdx.x < s) sdata[threadIdx.x] += sdata[threadIdx.x + s];
        __syncthreads();
    }

    // -------- Arrival + last-block finalize (unchanged) ---------------------
    __shared__ bool s_isLast;
    if (threadIdx.x == 0) {
        g_partials[blockIdx.x] = sdata[0];
        __threadfence();
        unsigned v = atomicInc(&g_count, gridDim.x - 1);   // wraps -> replay-safe
        s_isLast = (v == gridDim.x - 1);
    }
    __syncthreads();

    if (s_isLast) {
        double facc = 0.0;
        for (int k = threadIdx.x; k < NBLK; k += NTHR) facc += g_partials[k];
        sdata[threadIdx.x] = facc;
        __syncthreads();
        for (int s = NTHR/2; s > 0; s >>= 1) {
            if (threadIdx.x < s) sdata[threadIdx.x] += sdata[threadIdx.x + s];
            __syncthreads();
        }
        if (threadIdx.x == 0) {
            float  sf = (float)sdata[0];        // mimic jnp.sum's fp32 result
            double nn = trunc((double)sf);
            double tt = (nn > 1.0) ? nn * (nn - 1.0) * 0.5 : 0.0;
            g_total = (float)tt;
            __threadfence();
            g_epoch = g_epoch + 1;              // release
        }
        __syncthreads();
    } else {
        if (threadIdx.x == 0) {
            while (g_epoch == epoch0) { __nanosleep(64); }
            __threadfence();
        }
        __syncthreads();
    }

    __shared__ float s_t;
    if (threadIdx.x == 0) s_t = g_total;
    __syncthreads();
    const float t = s_t;

    // -------- Phase 2: out = x + t, ASCENDING, ASYNC BULK STORES ------------
    // Loads stay LDG (__ldcs: don't pollute the phase-1 residue). Results are
    // staged in smem and stored by ONE cp.async.bulk (32 KB) per chunk on the
    // async proxy — stores never occupy the warps' LSU scoreboards, so the
    // load stream free-runs. Double-buffered: wait_group<1> keeps at most one
    // store in flight per buffer. evict_first L2 policy on the bulk stores
    // preserves the x residue for the reuse window.
    unsigned long long pol;
    asm("createpolicy.fractional.L2::evict_first.b64 %0, 1.0;" : "=l"(pol));

    long long it = 0;
    for (long long c = blockIdx.x; c < nch; c += NBLK, it++) {
        const float4* src = x4 + c * CHUNK + threadIdx.x;
        float4 v0 = __ldcs(src);
        float4 v1 = __ldcs(src + 512);
        float4 v2 = __ldcs(src + 1024);
        float4 v3 = __ldcs(src + 1536);
        v0.x += t; v0.y += t; v0.z += t; v0.w += t;
        v1.x += t; v1.y += t; v1.z += t; v1.w += t;
        v2.x += t; v2.y += t; v2.z += t; v2.w += t;
        v3.x += t; v3.y += t; v3.z += t; v3.w += t;

        // Buffer (it&1) was last used by the bulk store issued 2 iterations
        // ago; wait until at most 1 group (last iteration's) is pending.
        if (threadIdx.x == 0)
            asm volatile("cp.async.bulk.wait_group 1;" ::: "memory");
        __syncthreads();

        float4* b = sbuf + (it & 1) * CHUNK;
        b[threadIdx.x]        = v0;
        b[threadIdx.x + 512]  = v1;
        b[threadIdx.x + 1024] = v2;
        b[threadIdx.x + 1536] = v3;
        asm volatile("fence.proxy.async.shared::cta;" ::: "memory");
        __syncthreads();

        if (threadIdx.x == 0) {
            const float4* gdst = out4 + c * CHUNK;
            unsigned saddr = smem_u32(b);
            asm volatile(
                "cp.async.bulk.global.shared::cta.bulk_group.L2::cache_hint "
                "[%0], [%1], %2, %3;"
                :: "l"(gdst), "r"(saddr), "r"((unsigned)CHUNK_BYTES), "l"(pol)
                : "memory");
            asm volatile("cp.async.bulk.commit_group;" ::: "memory");
        }
    }
    if (threadIdx.x == 0)
        asm volatile("cp.async.bulk.wait_group 0;" ::: "memory");
    __syncthreads();

    for (long long i = n4_main + tid; i < n4; i += gstride) {   // tail (empty here)
        float4 v = __ldcs(&x4[i]);
        v.x += t; v.y += t; v.z += t; v.w += t;
        __stcs(&out4[i], v);
    }
}

extern "C" void kernel_launch(void* const* d_in, const int* in_sizes, int n_in,
                              void* d_out, int out_size)
{
    const float4* x4   = (const float4*)d_in[0];
    float4*       out4 = (float4*)d_out;
    long long n  = (long long)in_sizes[0];   // 8192*8192
    long long n4 = n >> 2;

    static bool attr_done = false;           // host-side idempotent attr set
    if (!attr_done) {
        cudaFuncSetAttribute(fused_kernel,
                             cudaFuncAttributeMaxDynamicSharedMemorySize, 65536);
        attr_done = true;
    }
    fused_kernel<<<NBLK, NTHR, 65536>>>(x4, out4, n4);
}